// round 15
// baseline (speedup 1.0000x reference)
#include <cuda_runtime.h>

#define NN 64
#define CC 64
#define TT 300
#define VV 25
#define SS 3
#define OO 64
#define TCH 5            // frames per chunk
#define PCH (TCH*VV)     // 125 columns per tile
#define PS  128          // padded smem column stride
#define ZPS 72           // padded stride for transposed Z in kE
#define APS 28           // padded stride for A_eff in kE phase 2 (16B-aligned rows)
#define NCHUNK (TT/TCH)  // 60
#define THL 150          // kCD half length
#define SE2R 168         // kCD se2 rows (166 used)
#define SE2W 66          // kCD se2 stride (transposed layout [t][c])
#define S1W 160          // kCD s1 stride (158 used)

typedef unsigned long long u64;
__device__ __forceinline__ void ffma2(u64 &d, u64 a, u64 b) {
    asm("fma.rn.f32x2 %0, %1, %2, %0;" : "+l"(d) : "l"(a), "l"(b));
}
__device__ __forceinline__ u64 dup2(float a) {
    u64 r; asm("mov.b64 %0, {%1, %1};" : "=l"(r) : "f"(a)); return r;
}
__device__ __forceinline__ void unpk2(float &lo, float &hi, u64 v) {
    asm("mov.b64 {%0, %1}, %2;" : "=f"(lo), "=f"(hi) : "l"(v));
}

// ---------------- device scratch (no allocations allowed) ----------------
__device__ float d_Mt[SS*64*64];       // Mt[i][k][r] = M_i[r][k]
__device__ float d_ua[SS*64];
__device__ float d_wdt[SS*64*64];      // wdt[i][c][o] = wd[i][o][c]
__device__ float d_w1p[SS*9216];       // w1 channel-paired: [(j*9+k)*64 + c] = w1[i][j][c][k]
__device__ float d_bdsum[64];
__device__ float d_gram[SS*NN*VV*VV];
__device__ float d_termA[SS*NN*VV];
__device__ float d_sein[NN*CC*TT];
__device__ float d_A[SS*NN*VV*VV];
__device__ float d_g[SS*NN*TT];

// ---------------- kernel A ----------------
__global__ void kA(const float* __restrict__ wa, const float* __restrict__ wb,
                   const float* __restrict__ bb, const float* __restrict__ bd,
                   const float* __restrict__ wd, const float* __restrict__ w1g) {
    __shared__ float sa[4096], sb[4096];
    int i = blockIdx.x, tid = threadIdx.x;
    int gtid = i*256 + tid;
    for (int idx = gtid; idx < SS*NN*VV*VV; idx += SS*256) d_gram[idx] = 0.f;
    for (int idx = gtid; idx < SS*NN*VV;    idx += SS*256) d_termA[idx] = 0.f;

    for (int idx = tid; idx < 4096; idx += 256) {
        sa[idx] = wa[i*4096 + idx];
        sb[idx] = wb[i*4096 + idx];
    }
    __syncthreads();
    for (int idx = tid; idx < 4096; idx += 256) {
        int k = idx >> 6, r = idx & 63;
        float s = 0.f;
        #pragma unroll 8
        for (int o = 0; o < 64; o++) s += sa[o*64 + r] * sb[o*64 + k];
        d_Mt[i*4096 + idx] = s;
    }
    for (int idx = tid; idx < 4096; idx += 256) {
        int c = idx >> 6, o = idx & 63;
        d_wdt[i*4096 + idx] = wd[i*4096 + o*64 + c];
    }
    // w1 repack: d_w1p[i][(j*9+k)*64 + c] = w1[i][j][c][k]
    for (int idx = tid; idx < 9216; idx += 256) {
        int jk = idx >> 6, c = idx & 63;     // jk = j*9+k
        int j = jk / 9, k = jk - j*9;
        d_w1p[i*9216 + idx] = w1g[((i*16 + j)*64 + c)*9 + k];
    }
    if (tid < 64) {
        float s = 0.f;
        #pragma unroll 8
        for (int o = 0; o < 64; o++) s += sa[o*64 + tid] * bb[i*64 + o];
        d_ua[i*64 + tid] = s;
    }
    if (i == 0 && tid < 64)
        d_bdsum[tid] = bd[tid] + bd[64 + tid] + bd[128 + tid];
}

// ---------------- kernel B (R10/R12 config, unchanged) ----------------
__global__ void __launch_bounds__(256, 2) kB(const float* __restrict__ x) {
    extern __shared__ float sm[];
    float* xs  = sm;               // 64 x 128
    float* zs  = xs + 64*PS;       // 64 x 128
    float* msd = zs + 64*PS;       // 64 x 128 (Mt duplicated)
    float* gsm = msd + 64*128;     // SS x 625

    int tid = threadIdx.x;
    int chunk = blockIdx.x, n = blockIdx.y;
    int t0 = chunk * TCH;
    const float* xb = x + ((size_t)n*CC*TT + t0)*VV;

    for (int idx = tid; idx < CC*PCH; idx += 256) {
        int c = idx / PCH, pp = idx - c*PCH;
        xs[c*PS + pp] = xb[(size_t)c*TT*VV + pp];
    }
    for (int idx = tid; idx < CC*(PS-PCH); idx += 256) {
        int c = idx / (PS-PCH), pp = idx - c*(PS-PCH);
        xs[c*PS + PCH + pp] = 0.f;
    }
    for (int idx = tid; idx < SS*VV*VV; idx += 256) gsm[idx] = 0.f;
    __syncthreads();

    for (int idx = tid; idx < CC*TCH; idx += 256) {
        int c = idx / TCH, tl = idx - c*TCH;
        float s = 0.f;
        #pragma unroll
        for (int v = 0; v < VV; v++) s += xs[c*PS + tl*VV + v];
        d_sein[(n*CC + c)*TT + t0 + tl] = s * (1.f/VV);
    }
    if (tid < SS*VV) {
        int i = tid / VV, v1 = tid - i*VV;
        float s = 0.f;
        for (int c = 0; c < CC; c++) {
            float u = d_ua[i*64 + c];
            #pragma unroll
            for (int tl = 0; tl < TCH; tl++) s += u * xs[c*PS + tl*VV + v1];
        }
        atomicAdd(&d_termA[(i*NN + n)*VV + v1], s);
    }

    int w = tid >> 5, l = tid & 31;
    int r0m = (tid >> 5) * 8;
    int p0m = (tid & 31) * 4;
    int v1g = l / 5, v2g = l - v1g*5;

    for (int i = 0; i < SS; i++) {
        __syncthreads();
        for (int idx = tid; idx < 4096; idx += 256)
            *(u64*)&msd[2*idx] = dup2(d_Mt[i*4096 + idx]);
        __syncthreads();
        {
            u64 acc[8][2];
            #pragma unroll
            for (int r = 0; r < 8; r++) { acc[r][0] = 0ull; acc[r][1] = 0ull; }
            #pragma unroll 2
            for (int k = 0; k < 64; k++) {
                const ulonglong2* mp = (const ulonglong2*)&msd[k*128 + 2*r0m];
                ulonglong2 m0 = mp[0], m1 = mp[1], m2 = mp[2], m3 = mp[3];
                ulonglong2 bx = *(const ulonglong2*)&xs[k*PS + p0m];
                u64 md[8] = {m0.x, m0.y, m1.x, m1.y, m2.x, m2.y, m3.x, m3.y};
                #pragma unroll
                for (int r = 0; r < 8; r++) {
                    ffma2(acc[r][0], md[r], bx.x);
                    ffma2(acc[r][1], md[r], bx.y);
                }
            }
            #pragma unroll
            for (int r = 0; r < 8; r++) {
                ulonglong2 s0; s0.x = acc[r][0]; s0.y = acc[r][1];
                *(ulonglong2*)&zs[(r0m+r)*PS + p0m] = s0;
            }
        }
        __syncthreads();
        if (l < 25) {
            float gacc[5][5];
            #pragma unroll
            for (int a = 0; a < 5; a++)
                #pragma unroll
                for (int b = 0; b < 5; b++) gacc[a][b] = 0.f;
            for (int kk = w; kk < CC*TCH; kk += 8) {
                int c = kk / TCH, tl = kk - c*TCH;
                int base = c*PS + tl*VV;
                float xv[5], zv[5];
                #pragma unroll
                for (int j = 0; j < 5; j++) xv[j] = xs[base + v1g*5 + j];
                #pragma unroll
                for (int j = 0; j < 5; j++) zv[j] = zs[base + v2g*5 + j];
                #pragma unroll
                for (int a = 0; a < 5; a++)
                    #pragma unroll
                    for (int b = 0; b < 5; b++) gacc[a][b] += xv[a] * zv[b];
            }
            #pragma unroll
            for (int a = 0; a < 5; a++)
                #pragma unroll
                for (int b = 0; b < 5; b++)
                    atomicAdd(&gsm[i*VV*VV + (v1g*5 + a)*VV + v2g*5 + b], gacc[a][b]);
        }
    }
    __syncthreads();
    for (int idx = tid; idx < SS*VV*VV; idx += 256) {
        int i = idx / (VV*VV), rem = idx - i*VV*VV;
        atomicAdd(&d_gram[(i*NN + n)*VV*VV + rem], gsm[idx]);
    }
}

// ---------------- kernel CD: softmax + TemporalSE (2 T-halves, paired-channel conv1) ----------------
__global__ void __launch_bounds__(256) kCD(const float* __restrict__ PA, const float* __restrict__ alpha,
                                           const float* __restrict__ b1g,
                                           const float* __restrict__ w2g, const float* __restrict__ b2g) {
    extern __shared__ float sm[];
    float* se2  = sm;               // SE2R x SE2W  (transposed: se2[jj][c])
    float* w1ps = se2 + SE2R*SE2W;  // 9216 (paired w1)
    float* s1   = w1ps + 9216;      // 16 x S1W
    float* w2s  = s1 + 16*S1W;      // 144

    int b = blockIdx.x;
    int i = b / (NN*2);
    int rem = b - i*(NN*2);
    int n = rem >> 1, h = rem & 1;
    int tid = threadIdx.x;
    int tbase = h*THL;

    if (h == 0 && tid < VV) {
        int v2 = tid;
        float al = alpha[0];
        const float inv = 1.f / (float)(OO * TT);
        const float* gp = &d_gram[(i*NN + n)*VV*VV];
        const float* tp = &d_termA[(i*NN + n)*VV];
        float vals[VV];
        float mx = -1e30f;
        #pragma unroll
        for (int v1 = 0; v1 < VV; v1++) {
            float v = (gp[v1*VV + v2] + tp[v1]) * inv;
            vals[v1] = v;
            mx = fmaxf(mx, v);
        }
        float s = 0.f;
        #pragma unroll
        for (int v1 = 0; v1 < VV; v1++) { vals[v1] = expf(vals[v1] - mx); s += vals[v1]; }
        float rs = 1.f / s;
        #pragma unroll
        for (int v1 = 0; v1 < VV; v1++)
            d_A[((i*NN + n)*VV + v1)*VV + v2] = PA[i*VV*VV + v1*VV + v2] + al * vals[v1] * rs;
    }

    // se2 fill (transposed): se2[jj][c], jj -> t = tbase - 8 + jj. jj-inner for coalesced LDG.
    for (int idx = tid; idx < 64*SE2R; idx += 256) {
        int c = idx / SE2R, jj = idx - c*SE2R;
        int t = tbase - 8 + jj;
        se2[jj*SE2W + c] = (t >= 0 && t < TT) ? d_sein[(n*64 + c)*TT + t] : 0.f;
    }
    for (int idx = tid; idx < 9216; idx += 256) w1ps[idx] = d_w1p[i*9216 + idx];
    if (tid < 144) w2s[tid] = w2g[i*144 + tid];
    for (int idx = tid; idx < 16*S1W; idx += 256) s1[idx] = 0.f;
    __syncthreads();

    // conv1 + relu: paired over channels. thread (j = tid>>4, tg = tid&15), e0 = tg*10.
    {
        int j = tid >> 4, tg = tid & 15;
        int e0 = tg * 10;
        u64 acc2[10];
        #pragma unroll
        for (int tt = 0; tt < 10; tt++) acc2[tt] = 0ull;
        const u64* wrow = (const u64*)&w1ps[(j*9)*64];   // wrow[k*32 + cp]
        for (int cp = 0; cp < 32; cp++) {
            u64 win2[18];
            #pragma unroll
            for (int ww = 0; ww < 18; ww++)
                win2[ww] = *(const u64*)&se2[(e0 + ww)*SE2W + 2*cp];
            #pragma unroll
            for (int k = 0; k < 9; k++) {
                u64 wv = wrow[k*32 + cp];
                #pragma unroll
                for (int tt = 0; tt < 10; tt++) ffma2(acc2[tt], wv, win2[tt + k]);
            }
        }
        float bb1 = b1g[i*16 + j];
        #pragma unroll
        for (int tt = 0; tt < 10; tt++) {
            int e = e0 + tt;
            int t = tbase - 4 + e;
            if (e < 158 && t >= 0 && t < TT) {
                float lo, hi; unpk2(lo, hi, acc2[tt]);
                float v = lo + hi + bb1;
                s1[j*S1W + e] = v > 0.f ? v : 0.f;
            }
        }
    }
    __syncthreads();
    float bb2 = b2g[i];
    for (int u = tid; u < THL; u += 256) {
        float s = bb2;
        #pragma unroll
        for (int j = 0; j < 16; j++) {
            const float* wp = &w2s[j*9];
            #pragma unroll
            for (int k = 0; k < 9; k++) s += wp[k] * s1[j*S1W + u + k];
        }
        d_g[(i*NN + n)*TT + tbase + u] = 1.f + 1.f / (1.f + expf(-s));
    }
}

// ---------------- kernel E (R12 config): out = bdsum + sum_i g_i*((wd_i@x)@A_i) ----------------
__global__ void __launch_bounds__(256, 2) kE(const float* __restrict__ x, float* __restrict__ out) {
    extern __shared__ float sm[];
    float* xs  = sm;               // 64 x 128
    float* zt  = xs + 64*PS;       // 128 x 72 (Zt[p][o])
    float* ws  = zt + 128*ZPS;     // 64 x 64 (wdt: [c][o], natural o-pairs)
    float* As2 = ws + 4096;        // 25 x 28

    int tid = threadIdx.x;
    int chunk = blockIdx.x, n = blockIdx.y;
    int t0 = chunk * TCH;
    const float* xb = x + ((size_t)n*CC*TT + t0)*VV;

    for (int idx = tid; idx < CC*PCH; idx += 256) {
        int c = idx / PCH, pp = idx - c*PCH;
        xs[c*PS + pp] = xb[(size_t)c*TT*VV + pp];
    }
    for (int idx = tid; idx < CC*(PS-PCH); idx += 256) {
        int c = idx / (PS-PCH), pp = idx - c*(PS-PCH);
        xs[c*PS + PCH + pp] = 0.f;
    }

    int o0 = tid & 63, tl0 = tid >> 6;           // phase-2 unit A
    int pE = (tid >> 5)*16 + ((tid >> 4) & 1)*8; // mix: 8 p-rows per half-warp
    int oE = (tid & 15) * 4;                     // mix: 4 o-cols per lane

    u64 acc0p[12], acc1p[12];
    float acc0s = 0.f, acc1s = 0.f;
    #pragma unroll
    for (int j = 0; j < 12; j++) { acc0p[j] = 0ull; acc1p[j] = 0ull; }

    for (int i = 0; i < SS; i++) {
        __syncthreads();
        for (int idx = tid; idx < 4096; idx += 256) ws[idx] = d_wdt[i*4096 + idx];
        for (int idx = tid; idx < VV*VV; idx += 256) {
            int v1 = idx / VV, v2 = idx - v1*VV;
            As2[v1*APS + v2] = d_A[(i*NN + n)*VV*VV + idx];
        }
        __syncthreads();
        // phase 1: Zt[p][o] = sum_c x[c][p] * wdt[c][o]; 8p x 4o, natural w pairs
        {
            u64 acc[8][2];
            #pragma unroll
            for (int r = 0; r < 8; r++) { acc[r][0] = 0ull; acc[r][1] = 0ull; }
            #pragma unroll 2
            for (int k = 0; k < 64; k++) {
                float4 xa = *(const float4*)&xs[k*PS + pE];
                float4 xc = *(const float4*)&xs[k*PS + pE + 4];
                ulonglong2 wv = *(const ulonglong2*)&ws[k*64 + oE];
                float xv[8] = {xa.x, xa.y, xa.z, xa.w, xc.x, xc.y, xc.z, xc.w};
                #pragma unroll
                for (int r = 0; r < 8; r++) {
                    u64 xd = dup2(xv[r]);
                    ffma2(acc[r][0], xd, wv.x);
                    ffma2(acc[r][1], xd, wv.y);
                }
            }
            #pragma unroll
            for (int r = 0; r < 8; r++) {
                ulonglong2 s0; s0.x = acc[r][0]; s0.y = acc[r][1];
                *(ulonglong2*)&zt[(pE+r)*ZPS + oE] = s0;
            }
        }
        __syncthreads();
        // phase 2: acc[v2] += g * sum_v1 Zt[tl*25+v1][o] * A[v1][v2]
        {
            float g0 = d_g[(i*NN + n)*TT + t0 + tl0];
            #pragma unroll 5
            for (int v1 = 0; v1 < VV; v1++) {
                float wg = g0 * zt[(tl0*VV + v1)*ZPS + o0];
                u64 wg2 = dup2(wg);
                const ulonglong2* ap = (const ulonglong2*)&As2[v1*APS];
                #pragma unroll
                for (int jj = 0; jj < 6; jj++) {
                    ulonglong2 av = ap[jj];
                    ffma2(acc0p[2*jj],   wg2, av.x);
                    ffma2(acc0p[2*jj+1], wg2, av.y);
                }
                acc0s += wg * As2[v1*APS + 24];
            }
            if (tid < 64) {
                float g1 = d_g[(i*NN + n)*TT + t0 + 4];
                #pragma unroll 5
                for (int v1 = 0; v1 < VV; v1++) {
                    float wg = g1 * zt[(4*VV + v1)*ZPS + tid];
                    u64 wg2 = dup2(wg);
                    const ulonglong2* ap = (const ulonglong2*)&As2[v1*APS];
                    #pragma unroll
                    for (int jj = 0; jj < 6; jj++) {
                        ulonglong2 av = ap[jj];
                        ffma2(acc1p[2*jj],   wg2, av.x);
                        ffma2(acc1p[2*jj+1], wg2, av.y);
                    }
                    acc1s += wg * As2[v1*APS + 24];
                }
            }
        }
    }

    float bo = d_bdsum[o0];
    float* op = out + (((size_t)n*OO + o0)*TT + t0 + tl0)*VV;
    #pragma unroll
    for (int j = 0; j < 12; j++) {
        float lo, hi; unpk2(lo, hi, acc0p[j]);
        op[2*j]   = lo + bo;
        op[2*j+1] = hi + bo;
    }
    op[24] = acc0s + bo;
    if (tid < 64) {
        float bo1 = d_bdsum[tid];
        float* op1 = out + (((size_t)n*OO + tid)*TT + t0 + 4)*VV;
        #pragma unroll
        for (int j = 0; j < 12; j++) {
            float lo, hi; unpk2(lo, hi, acc1p[j]);
            op1[2*j]   = lo + bo1;
            op1[2*j+1] = hi + bo1;
        }
        op1[24] = acc1s + bo1;
    }
}

// ---------------- launcher ----------------
extern "C" void kernel_launch(void* const* d_in, const int* in_sizes, int n_in,
                              void* d_out, int out_size) {
    const float* x     = (const float*)d_in[0];
    const float* PA    = (const float*)d_in[1];
    const float* alpha = (const float*)d_in[2];
    const float* wa    = (const float*)d_in[3];
    // d_in[4] = ba: cancels in softmax, unused
    const float* wb    = (const float*)d_in[5];
    const float* bb    = (const float*)d_in[6];
    const float* w1    = (const float*)d_in[7];
    const float* b1    = (const float*)d_in[8];
    const float* w2    = (const float*)d_in[9];
    const float* b2    = (const float*)d_in[10];
    const float* wd    = (const float*)d_in[11];
    const float* bd    = (const float*)d_in[12];
    float* out = (float*)d_out;

    const int SMEM_B = (64*PS*2 + 64*128 + SS*VV*VV) * 4;     // 105788
    const int SMEM_E = (64*PS + 128*ZPS + 4096 + VV*APS) * 4; // 88816
    const int SMEM_D = (SE2R*SE2W + 9216 + 16*S1W + 144) * 4; // 92032

    cudaFuncSetAttribute(kB,  cudaFuncAttributeMaxDynamicSharedMemorySize, SMEM_B);
    cudaFuncSetAttribute(kCD, cudaFuncAttributeMaxDynamicSharedMemorySize, SMEM_D);
    cudaFuncSetAttribute(kE,  cudaFuncAttributeMaxDynamicSharedMemorySize, SMEM_E);

    kA<<<SS, 256>>>(wa, wb, bb, bd, wd, w1);
    kB<<<dim3(NCHUNK, NN), 256, SMEM_B>>>(x);
    kCD<<<SS*NN*2, 256, SMEM_D>>>(PA, alpha, b1, w2, b2);
    kE<<<dim3(NCHUNK, NN), 256, SMEM_E>>>(x, out);
    (void)in_sizes; (void)n_in; (void)out_size;
}

// round 16
// speedup vs baseline: 1.0440x; 1.0440x over previous
#include <cuda_runtime.h>

#define NN 64
#define CC 64
#define TT 300
#define VV 25
#define SS 3
#define OO 64
#define TCH 5            // frames per chunk
#define PCH (TCH*VV)     // 125 columns per tile
#define PS  128          // padded smem column stride
#define ZPS 72           // padded stride for transposed Z in kE
#define APS 28           // padded stride for A_eff in kE phase 2 (16B-aligned rows)
#define NCHUNK (TT/TCH)  // 60
#define THL 150          // kCD half length
#define SEW 168          // kCD se stride (166 used)
#define S1W 160          // kCD s1 stride (158 used)

typedef unsigned long long u64;
__device__ __forceinline__ void ffma2(u64 &d, u64 a, u64 b) {
    asm("fma.rn.f32x2 %0, %1, %2, %0;" : "+l"(d) : "l"(a), "l"(b));
}
__device__ __forceinline__ u64 dup2(float a) {
    u64 r; asm("mov.b64 %0, {%1, %1};" : "=l"(r) : "f"(a)); return r;
}
__device__ __forceinline__ void unpk2(float &lo, float &hi, u64 v) {
    asm("mov.b64 {%0, %1}, %2;" : "=f"(lo), "=f"(hi) : "l"(v));
}

// ---------------- device scratch (no allocations allowed) ----------------
__device__ float d_Mt[SS*64*64];       // Mt[i][k][r] = M_i[r][k]
__device__ float d_ua[SS*64];
__device__ float d_wdt[SS*64*64];      // wdt[i][c][o] = wd[i][o][c]
__device__ float d_bdsum[64];
__device__ float d_gram[SS*NN*VV*VV];
__device__ float d_termA[SS*NN*VV];
__device__ float d_sein[NN*CC*TT];
__device__ float d_A[SS*NN*VV*VV];
__device__ float d_g[SS*NN*TT];

// ---------------- kernel A (R12) ----------------
__global__ void kA(const float* __restrict__ wa, const float* __restrict__ wb,
                   const float* __restrict__ bb, const float* __restrict__ bd,
                   const float* __restrict__ wd) {
    __shared__ float sa[4096], sb[4096];
    int i = blockIdx.x, tid = threadIdx.x;
    int gtid = i*256 + tid;
    for (int idx = gtid; idx < SS*NN*VV*VV; idx += SS*256) d_gram[idx] = 0.f;
    for (int idx = gtid; idx < SS*NN*VV;    idx += SS*256) d_termA[idx] = 0.f;

    for (int idx = tid; idx < 4096; idx += 256) {
        sa[idx] = wa[i*4096 + idx];
        sb[idx] = wb[i*4096 + idx];
    }
    __syncthreads();
    for (int idx = tid; idx < 4096; idx += 256) {
        int k = idx >> 6, r = idx & 63;
        float s = 0.f;
        #pragma unroll 8
        for (int o = 0; o < 64; o++) s += sa[o*64 + r] * sb[o*64 + k];
        d_Mt[i*4096 + idx] = s;
    }
    for (int idx = tid; idx < 4096; idx += 256) {
        int c = idx >> 6, o = idx & 63;
        d_wdt[i*4096 + idx] = wd[i*4096 + o*64 + c];
    }
    if (tid < 64) {
        float s = 0.f;
        #pragma unroll 8
        for (int o = 0; o < 64; o++) s += sa[o*64 + tid] * bb[i*64 + o];
        d_ua[i*64 + tid] = s;
    }
    if (i == 0 && tid < 64)
        d_bdsum[tid] = bd[tid] + bd[64 + tid] + bd[128 + tid];
}

// ---------------- kernel B: gram via staged reduction (no smem atomics) ----------------
__global__ void __launch_bounds__(256, 2) kB(const float* __restrict__ x) {
    extern __shared__ float sm[];
    float* xs  = sm;               // 64 x 128
    float* zs  = xs + 64*PS;       // 64 x 128
    float* msd = zs + 64*PS;       // 64 x 128 (Mt duplicated) -- REUSED as gram staging (8x625 <= 8192)
    float* gsm = msd + 64*128;     // SS x 625

    int tid = threadIdx.x;
    int chunk = blockIdx.x, n = blockIdx.y;
    int t0 = chunk * TCH;
    const float* xb = x + ((size_t)n*CC*TT + t0)*VV;

    for (int idx = tid; idx < CC*PCH; idx += 256) {
        int c = idx / PCH, pp = idx - c*PCH;
        xs[c*PS + pp] = xb[(size_t)c*TT*VV + pp];
    }
    for (int idx = tid; idx < CC*(PS-PCH); idx += 256) {
        int c = idx / (PS-PCH), pp = idx - c*(PS-PCH);
        xs[c*PS + PCH + pp] = 0.f;
    }
    __syncthreads();

    // se_in: mean over V (grid-stride: CC*TCH = 320 > 256)
    for (int idx = tid; idx < CC*TCH; idx += 256) {
        int c = idx / TCH, tl = idx - c*TCH;
        float s = 0.f;
        #pragma unroll
        for (int v = 0; v < VV; v++) s += xs[c*PS + tl*VV + v];
        d_sein[(n*CC + c)*TT + t0 + tl] = s * (1.f/VV);
    }
    // termA partial
    if (tid < SS*VV) {
        int i = tid / VV, v1 = tid - i*VV;
        float s = 0.f;
        for (int c = 0; c < CC; c++) {
            float u = d_ua[i*64 + c];
            #pragma unroll
            for (int tl = 0; tl < TCH; tl++) s += u * xs[c*PS + tl*VV + v1];
        }
        atomicAdd(&d_termA[(i*NN + n)*VV + v1], s);
    }

    int w = tid >> 5, l = tid & 31;
    int r0m = (tid >> 5) * 8;
    int p0m = (tid & 31) * 4;
    int v1g = l / 5, v2g = l - v1g*5;

    for (int i = 0; i < SS; i++) {
        __syncthreads();   // staging reads done (prev subset) -> msd reload safe
        for (int idx = tid; idx < 4096; idx += 256)
            *(u64*)&msd[2*idx] = dup2(d_Mt[i*4096 + idx]);
        __syncthreads();
        // phase 1: Z[r][p] = sum_k M[r][k] x[k][p]; 8r x 4p, FFMA2
        {
            u64 acc[8][2];
            #pragma unroll
            for (int r = 0; r < 8; r++) { acc[r][0] = 0ull; acc[r][1] = 0ull; }
            #pragma unroll 2
            for (int k = 0; k < 64; k++) {
                const ulonglong2* mp = (const ulonglong2*)&msd[k*128 + 2*r0m];
                ulonglong2 m0 = mp[0], m1 = mp[1], m2 = mp[2], m3 = mp[3];
                ulonglong2 bx = *(const ulonglong2*)&xs[k*PS + p0m];
                u64 md[8] = {m0.x, m0.y, m1.x, m1.y, m2.x, m2.y, m3.x, m3.y};
                #pragma unroll
                for (int r = 0; r < 8; r++) {
                    ffma2(acc[r][0], md[r], bx.x);
                    ffma2(acc[r][1], md[r], bx.y);
                }
            }
            #pragma unroll
            for (int r = 0; r < 8; r++) {
                ulonglong2 s0; s0.x = acc[r][0]; s0.y = acc[r][1];
                *(ulonglong2*)&zs[(r0m+r)*PS + p0m] = s0;
            }
        }
        __syncthreads();   // zs ready; msd reads done -> staging writes safe
        // gram: lane owns 5x5 tile, warp owns rows w::8; write to per-warp staging
        if (l < 25) {
            float gacc[5][5];
            #pragma unroll
            for (int a = 0; a < 5; a++)
                #pragma unroll
                for (int b = 0; b < 5; b++) gacc[a][b] = 0.f;
            for (int kk = w; kk < CC*TCH; kk += 8) {
                int c = kk / TCH, tl = kk - c*TCH;
                int base = c*PS + tl*VV;
                float xv[5], zv[5];
                #pragma unroll
                for (int j = 0; j < 5; j++) xv[j] = xs[base + v1g*5 + j];
                #pragma unroll
                for (int j = 0; j < 5; j++) zv[j] = zs[base + v2g*5 + j];
                #pragma unroll
                for (int a = 0; a < 5; a++)
                    #pragma unroll
                    for (int b = 0; b < 5; b++) gacc[a][b] += xv[a] * zv[b];
            }
            float* stg = &msd[w*625];
            #pragma unroll
            for (int a = 0; a < 5; a++)
                #pragma unroll
                for (int b = 0; b < 5; b++)
                    stg[(v1g*5 + a)*VV + v2g*5 + b] = gacc[a][b];
        }
        __syncthreads();   // staging complete
        // reduce 8 warp-slices -> gsm[i] (plain stores, no atomics)
        for (int idx = tid; idx < VV*VV; idx += 256) {
            float s = msd[idx] + msd[625 + idx] + msd[2*625 + idx] + msd[3*625 + idx]
                    + msd[4*625 + idx] + msd[5*625 + idx] + msd[6*625 + idx] + msd[7*625 + idx];
            gsm[i*VV*VV + idx] = s;
        }
    }
    __syncthreads();
    for (int idx = tid; idx < SS*VV*VV; idx += 256) {
        int i = idx / (VV*VV), rem = idx - i*VV*VV;
        atomicAdd(&d_gram[(i*NN + n)*VV*VV + rem], gsm[idx]);
    }
}

// ---------------- kernel CD (R12 split config) ----------------
__global__ void __launch_bounds__(256) kCD(const float* __restrict__ PA, const float* __restrict__ alpha,
                                           const float* __restrict__ w1g, const float* __restrict__ b1g,
                                           const float* __restrict__ w2g, const float* __restrict__ b2g) {
    extern __shared__ float sm[];
    float* se  = sm;               // 64 x SEW
    float* w1s = se + 64*SEW;      // 9216
    float* s1  = w1s + 9216;       // 16 x S1W
    float* w2s = s1 + 16*S1W;      // 144

    int b = blockIdx.x;
    int i = b / (NN*2);
    int rem = b - i*(NN*2);
    int n = rem >> 1, h = rem & 1;
    int tid = threadIdx.x;
    int tbase = h*THL;

    if (h == 0 && tid < VV) {
        int v2 = tid;
        float al = alpha[0];
        const float inv = 1.f / (float)(OO * TT);
        const float* gp = &d_gram[(i*NN + n)*VV*VV];
        const float* tp = &d_termA[(i*NN + n)*VV];
        float vals[VV];
        float mx = -1e30f;
        #pragma unroll
        for (int v1 = 0; v1 < VV; v1++) {
            float v = (gp[v1*VV + v2] + tp[v1]) * inv;
            vals[v1] = v;
            mx = fmaxf(mx, v);
        }
        float s = 0.f;
        #pragma unroll
        for (int v1 = 0; v1 < VV; v1++) { vals[v1] = expf(vals[v1] - mx); s += vals[v1]; }
        float rs = 1.f / s;
        #pragma unroll
        for (int v1 = 0; v1 < VV; v1++)
            d_A[((i*NN + n)*VV + v1)*VV + v2] = PA[i*VV*VV + v1*VV + v2] + al * vals[v1] * rs;
    }

    for (int idx = tid; idx < 64*SEW; idx += 256) {
        int c = idx / SEW, jj = idx - c*SEW;
        int t = tbase - 8 + jj;
        se[idx] = (jj < 166 && t >= 0 && t < TT) ? d_sein[(n*64 + c)*TT + t] : 0.f;
    }
    for (int idx = tid; idx < 9216; idx += 256) w1s[idx] = w1g[i*9216 + idx];
    if (tid < 144) w2s[tid] = w2g[i*144 + tid];
    for (int idx = tid; idx < 16*S1W; idx += 256) s1[idx] = 0.f;
    __syncthreads();

    {
        int j = tid >> 4, tg = tid & 15;
        int e0 = tg * 10;
        float bb1 = b1g[i*16 + j];
        float acc[10];
        #pragma unroll
        for (int tt = 0; tt < 10; tt++) acc[tt] = bb1;
        for (int c = 0; c < 64; c++) {
            float win[18];
            #pragma unroll
            for (int ww = 0; ww < 18; ww++) {
                int jj = e0 + ww;
                win[ww] = (jj < 166) ? se[c*SEW + jj] : 0.f;
            }
            const float* wp = &w1s[(j*64 + c)*9];
            #pragma unroll
            for (int k = 0; k < 9; k++) {
                float wv = wp[k];
                #pragma unroll
                for (int tt = 0; tt < 10; tt++) acc[tt] += wv * win[tt + k];
            }
        }
        #pragma unroll
        for (int tt = 0; tt < 10; tt++) {
            int e = e0 + tt;
            int t = tbase - 4 + e;
            if (e < 158 && t >= 0 && t < TT) {
                float v = acc[tt];
                s1[j*S1W + e] = v > 0.f ? v : 0.f;
            }
        }
    }
    __syncthreads();
    float bb2 = b2g[i];
    for (int u = tid; u < THL; u += 256) {
        float s = bb2;
        #pragma unroll
        for (int j = 0; j < 16; j++) {
            const float* wp = &w2s[j*9];
            #pragma unroll
            for (int k = 0; k < 9; k++) s += wp[k] * s1[j*S1W + u + k];
        }
        d_g[(i*NN + n)*TT + tbase + u] = 1.f + 1.f / (1.f + expf(-s));
    }
}

// ---------------- kernel E (R12 config) ----------------
__global__ void __launch_bounds__(256, 2) kE(const float* __restrict__ x, float* __restrict__ out) {
    extern __shared__ float sm[];
    float* xs  = sm;               // 64 x 128
    float* zt  = xs + 64*PS;       // 128 x 72 (Zt[p][o])
    float* ws  = zt + 128*ZPS;     // 64 x 64 (wdt: [c][o], natural o-pairs)
    float* As2 = ws + 4096;        // 25 x 28

    int tid = threadIdx.x;
    int chunk = blockIdx.x, n = blockIdx.y;
    int t0 = chunk * TCH;
    const float* xb = x + ((size_t)n*CC*TT + t0)*VV;

    for (int idx = tid; idx < CC*PCH; idx += 256) {
        int c = idx / PCH, pp = idx - c*PCH;
        xs[c*PS + pp] = xb[(size_t)c*TT*VV + pp];
    }
    for (int idx = tid; idx < CC*(PS-PCH); idx += 256) {
        int c = idx / (PS-PCH), pp = idx - c*(PS-PCH);
        xs[c*PS + PCH + pp] = 0.f;
    }

    int o0 = tid & 63, tl0 = tid >> 6;           // phase-2 unit A
    int pE = (tid >> 5)*16 + ((tid >> 4) & 1)*8; // mix: 8 p-rows per half-warp
    int oE = (tid & 15) * 4;                     // mix: 4 o-cols per lane

    u64 acc0p[12], acc1p[12];
    float acc0s = 0.f, acc1s = 0.f;
    #pragma unroll
    for (int j = 0; j < 12; j++) { acc0p[j] = 0ull; acc1p[j] = 0ull; }

    for (int i = 0; i < SS; i++) {
        __syncthreads();
        for (int idx = tid; idx < 4096; idx += 256) ws[idx] = d_wdt[i*4096 + idx];
        for (int idx = tid; idx < VV*VV; idx += 256) {
            int v1 = idx / VV, v2 = idx - v1*VV;
            As2[v1*APS + v2] = d_A[(i*NN + n)*VV*VV + idx];
        }
        __syncthreads();
        // phase 1: Zt[p][o] = sum_c x[c][p] * wdt[c][o]; 8p x 4o, natural w pairs
        {
            u64 acc[8][2];
            #pragma unroll
            for (int r = 0; r < 8; r++) { acc[r][0] = 0ull; acc[r][1] = 0ull; }
            #pragma unroll 2
            for (int k = 0; k < 64; k++) {
                float4 xa = *(const float4*)&xs[k*PS + pE];
                float4 xc = *(const float4*)&xs[k*PS + pE + 4];
                ulonglong2 wv = *(const ulonglong2*)&ws[k*64 + oE];
                float xv[8] = {xa.x, xa.y, xa.z, xa.w, xc.x, xc.y, xc.z, xc.w};
                #pragma unroll
                for (int r = 0; r < 8; r++) {
                    u64 xd = dup2(xv[r]);
                    ffma2(acc[r][0], xd, wv.x);
                    ffma2(acc[r][1], xd, wv.y);
                }
            }
            #pragma unroll
            for (int r = 0; r < 8; r++) {
                ulonglong2 s0; s0.x = acc[r][0]; s0.y = acc[r][1];
                *(ulonglong2*)&zt[(pE+r)*ZPS + oE] = s0;
            }
        }
        __syncthreads();
        // phase 2: acc[v2] += g * sum_v1 Zt[tl*25+v1][o] * A[v1][v2]
        {
            float g0 = d_g[(i*NN + n)*TT + t0 + tl0];
            #pragma unroll 5
            for (int v1 = 0; v1 < VV; v1++) {
                float wg = g0 * zt[(tl0*VV + v1)*ZPS + o0];
                u64 wg2 = dup2(wg);
                const ulonglong2* ap = (const ulonglong2*)&As2[v1*APS];
                #pragma unroll
                for (int jj = 0; jj < 6; jj++) {
                    ulonglong2 av = ap[jj];
                    ffma2(acc0p[2*jj],   wg2, av.x);
                    ffma2(acc0p[2*jj+1], wg2, av.y);
                }
                acc0s += wg * As2[v1*APS + 24];
            }
            if (tid < 64) {
                float g1 = d_g[(i*NN + n)*TT + t0 + 4];
                #pragma unroll 5
                for (int v1 = 0; v1 < VV; v1++) {
                    float wg = g1 * zt[(4*VV + v1)*ZPS + tid];
                    u64 wg2 = dup2(wg);
                    const ulonglong2* ap = (const ulonglong2*)&As2[v1*APS];
                    #pragma unroll
                    for (int jj = 0; jj < 6; jj++) {
                        ulonglong2 av = ap[jj];
                        ffma2(acc1p[2*jj],   wg2, av.x);
                        ffma2(acc1p[2*jj+1], wg2, av.y);
                    }
                    acc1s += wg * As2[v1*APS + 24];
                }
            }
        }
    }

    float bo = d_bdsum[o0];
    float* op = out + (((size_t)n*OO + o0)*TT + t0 + tl0)*VV;
    #pragma unroll
    for (int j = 0; j < 12; j++) {
        float lo, hi; unpk2(lo, hi, acc0p[j]);
        op[2*j]   = lo + bo;
        op[2*j+1] = hi + bo;
    }
    op[24] = acc0s + bo;
    if (tid < 64) {
        float bo1 = d_bdsum[tid];
        float* op1 = out + (((size_t)n*OO + tid)*TT + t0 + 4)*VV;
        #pragma unroll
        for (int j = 0; j < 12; j++) {
            float lo, hi; unpk2(lo, hi, acc1p[j]);
            op1[2*j]   = lo + bo1;
            op1[2*j+1] = hi + bo1;
        }
        op1[24] = acc1s + bo1;
    }
}

// ---------------- launcher ----------------
extern "C" void kernel_launch(void* const* d_in, const int* in_sizes, int n_in,
                              void* d_out, int out_size) {
    const float* x     = (const float*)d_in[0];
    const float* PA    = (const float*)d_in[1];
    const float* alpha = (const float*)d_in[2];
    const float* wa    = (const float*)d_in[3];
    // d_in[4] = ba: cancels in softmax, unused
    const float* wb    = (const float*)d_in[5];
    const float* bb    = (const float*)d_in[6];
    const float* w1    = (const float*)d_in[7];
    const float* b1    = (const float*)d_in[8];
    const float* w2    = (const float*)d_in[9];
    const float* b2    = (const float*)d_in[10];
    const float* wd    = (const float*)d_in[11];
    const float* bd    = (const float*)d_in[12];
    float* out = (float*)d_out;

    const int SMEM_B = (64*PS*2 + 64*128 + SS*VV*VV) * 4;     // 105788
    const int SMEM_E = (64*PS + 128*ZPS + 4096 + VV*APS) * 4; // 88816
    const int SMEM_D = (64*SEW + 9216 + 16*S1W + 144) * 4;    // 90688

    cudaFuncSetAttribute(kB,  cudaFuncAttributeMaxDynamicSharedMemorySize, SMEM_B);
    cudaFuncSetAttribute(kCD, cudaFuncAttributeMaxDynamicSharedMemorySize, SMEM_D);
    cudaFuncSetAttribute(kE,  cudaFuncAttributeMaxDynamicSharedMemorySize, SMEM_E);

    kA<<<SS, 256>>>(wa, wb, bb, bd, wd);
    kB<<<dim3(NCHUNK, NN), 256, SMEM_B>>>(x);
    kCD<<<SS*NN*2, 256, SMEM_D>>>(PA, alpha, w1, b1, w2, b2);
    kE<<<dim3(NCHUNK, NN), 256, SMEM_E>>>(x, out);
    (void)in_sizes; (void)n_in; (void)out_size;
}